// round 8
// baseline (speedup 1.0000x reference)
#include <cuda_runtime.h>
#include <cstdint>

#define BATCH    64
#define LSEQ     16384
#define FCH      128
#define KW       16
#define OUT_LEN  16369           // (16384 - 16) + 1
#define TILE_O   64              // o per block
#define NTHREADS 256             // 8 warps
#define BO       16              // o per thread, single diagonal block
#define XWIN     (BO + KW - 1)   // 31

typedef unsigned long long u64;

__device__ __forceinline__ u64 pack2(float lo, float hi) {
    u64 r;
    asm("mov.b64 %0, {%1, %2};" : "=l"(r) : "f"(lo), "f"(hi));
    return r;
}
__device__ __forceinline__ void ffma2(u64& d, u64 a, u64 b) {
    asm("fma.rn.f32x2 %0, %1, %2, %0;" : "+l"(d) : "l"(a), "l"(b));
}
__device__ __forceinline__ void fmul2(u64& d, u64 a, u64 b) {
    asm("mul.rn.f32x2 %0, %1, %2;" : "=l"(d) : "l"(a), "l"(b));
}
__device__ __forceinline__ void unpack2(u64 v, float& lo, float& hi) {
    asm("mov.b64 {%0, %1}, %2;" : "=f"(lo), "=f"(hi) : "l"(v));
}

// one diagonal update for output J at window step i (i is compile-time)
#define DIAG1(ACC, J)                                            \
    if (i == (J)) fmul2(ACC, xv, w[0]);                          \
    else if (i > (J) && i < (J) + KW) ffma2(ACC, xv, w[i - (J)]);

// relu + STG.64 for output J
#define STORE1(ACC, J)                                           \
    do {                                                         \
        float l_, h_;                                            \
        unpack2(ACC, l_, h_);                                    \
        float2 r_;                                               \
        r_.x = fmaxf(l_, 0.f);                                   \
        r_.y = fmaxf(h_, 0.f);                                   \
        po[(J) * (FCH / 2)] = r_;                                \
    } while (0)

__global__ __launch_bounds__(NTHREADS, 3)
void speccnn1d_kernel(const float* __restrict__ x,
                      const float* __restrict__ kern,
                      float* __restrict__ out) {
    __shared__ u64 xs2[TILE_O + KW];                     // {v,v} duplicated

    const int tid = threadIdx.x;
    const int b   = blockIdx.y;
    const int o0  = blockIdx.x * TILE_O;

    // ---- stage x window duplicated ----
    {
        const float* xb = x + (size_t)b * LSEQ;
        if (tid < TILE_O + KW - 1) {                     // 79 elements
            int xi = o0 + tid;
            float v = (xi < LSEQ) ? __ldg(&xb[xi]) : 0.0f;
            xs2[tid] = pack2(v, v);
        }
    }

    // thread -> (channel pair, o-subgroup); og warp-uniform => broadcast LDS
    const int f0 = ((tid & 31) << 1) + (((tid >> 5) & 1) << 6);  // even, 0..126
    const int og = tid >> 6;                                     // 0..3

    // ---- 2 weight rows -> 16 packed pairs (32 regs) ----
    u64 w[KW];
    {
        const float4* r0 = reinterpret_cast<const float4*>(kern + (size_t)f0 * KW);
        const float4* r1 = reinterpret_cast<const float4*>(kern + (size_t)(f0 + 1) * KW);
        #pragma unroll
        for (int q = 0; q < 4; q++) {
            float4 a = __ldg(&r0[q]);
            float4 c = __ldg(&r1[q]);
            w[q * 4 + 0] = pack2(a.x, c.x);
            w[q * 4 + 1] = pack2(a.y, c.y);
            w[q * 4 + 2] = pack2(a.z, c.z);
            w[q * 4 + 3] = pack2(a.w, c.w);
        }
    }
    __syncthreads();

    const int lo = og * BO;                              // local o
    const int o  = o0 + lo;
    const u64* xp = &xs2[lo];

    // ---- diagonal over 16 outputs, named scalar accumulators ----
    u64 A0, A1, A2, A3, A4, A5, A6, A7;
    u64 A8, A9, A10, A11, A12, A13, A14, A15;

    #pragma unroll
    for (int i = 0; i < XWIN; i++) {                     // 31 broadcast LDS.64
        u64 xv = xp[i];
        DIAG1(A0,  0)  DIAG1(A1,  1)  DIAG1(A2,  2)  DIAG1(A3,  3)
        DIAG1(A4,  4)  DIAG1(A5,  5)  DIAG1(A6,  6)  DIAG1(A7,  7)
        DIAG1(A8,  8)  DIAG1(A9,  9)  DIAG1(A10, 10) DIAG1(A11, 11)
        DIAG1(A12, 12) DIAG1(A13, 13) DIAG1(A14, 14) DIAG1(A15, 15)
    }

    float2* po = reinterpret_cast<float2*>(
        out + (size_t)b * OUT_LEN * FCH + (size_t)o * FCH + f0);

    if (o + BO <= OUT_LEN) {                             // fast path
        STORE1(A0,  0);  STORE1(A1,  1);  STORE1(A2,  2);  STORE1(A3,  3);
        STORE1(A4,  4);  STORE1(A5,  5);  STORE1(A6,  6);  STORE1(A7,  7);
        STORE1(A8,  8);  STORE1(A9,  9);  STORE1(A10, 10); STORE1(A11, 11);
        STORE1(A12, 12); STORE1(A13, 13); STORE1(A14, 14); STORE1(A15, 15);
    } else {
        const int rem = OUT_LEN - o;                     // 0..15 valid
        if (0  < rem) STORE1(A0,  0);
        if (1  < rem) STORE1(A1,  1);
        if (2  < rem) STORE1(A2,  2);
        if (3  < rem) STORE1(A3,  3);
        if (4  < rem) STORE1(A4,  4);
        if (5  < rem) STORE1(A5,  5);
        if (6  < rem) STORE1(A6,  6);
        if (7  < rem) STORE1(A7,  7);
        if (8  < rem) STORE1(A8,  8);
        if (9  < rem) STORE1(A9,  9);
        if (10 < rem) STORE1(A10, 10);
        if (11 < rem) STORE1(A11, 11);
        if (12 < rem) STORE1(A12, 12);
        if (13 < rem) STORE1(A13, 13);
        if (14 < rem) STORE1(A14, 14);
        if (15 < rem) STORE1(A15, 15);
    }
}

extern "C" void kernel_launch(void* const* d_in, const int* in_sizes, int n_in,
                              void* d_out, int out_size) {
    const float* x    = (const float*)d_in[0];   // (64, 16384) fp32
    const float* kern = (const float*)d_in[1];   // (128, 16)  fp32
    float* out        = (float*)d_out;           // (64, 16369, 128) fp32

    dim3 grid((OUT_LEN + TILE_O - 1) / TILE_O, BATCH);   // (256, 64)
    speccnn1d_kernel<<<grid, NTHREADS>>>(x, kern, out);
}

// round 9
// speedup vs baseline: 1.0779x; 1.0779x over previous
#include <cuda_runtime.h>
#include <cstdint>

#define BATCH    64
#define LSEQ     16384
#define FCH      128
#define KW       16
#define OUT_LEN  16369           // (16384 - 16) + 1
#define TILE_O   32              // o per block
#define NTHREADS 128             // 4 warps
#define BO       16              // o per thread, single diagonal block
#define XWIN     (BO + KW - 1)   // 31

typedef unsigned long long u64;

__device__ __forceinline__ u64 pack2(float lo, float hi) {
    u64 r;
    asm("mov.b64 %0, {%1, %2};" : "=l"(r) : "f"(lo), "f"(hi));
    return r;
}
__device__ __forceinline__ void ffma2(u64& d, u64 a, u64 b) {
    asm("fma.rn.f32x2 %0, %1, %2, %0;" : "+l"(d) : "l"(a), "l"(b));
}
__device__ __forceinline__ void fmul2(u64& d, u64 a, u64 b) {
    asm("mul.rn.f32x2 %0, %1, %2;" : "=l"(d) : "l"(a), "l"(b));
}
__device__ __forceinline__ void unpack2(u64 v, float& lo, float& hi) {
    asm("mov.b64 {%0, %1}, %2;" : "=f"(lo), "=f"(hi) : "l"(v));
}

// one diagonal update for output J at window step i (i is compile-time)
#define DIAG1(ACC, J)                                            \
    if (i == (J)) fmul2(ACC, xv, w[0]);                          \
    else if (i > (J) && i < (J) + KW) ffma2(ACC, xv, w[i - (J)]);

// relu + STG.64 for output J
#define STORE1(ACC, J)                                           \
    do {                                                         \
        float l_, h_;                                            \
        unpack2(ACC, l_, h_);                                    \
        float2 r_;                                               \
        r_.x = fmaxf(l_, 0.f);                                   \
        r_.y = fmaxf(h_, 0.f);                                   \
        po[(J) * (FCH / 2)] = r_;                                \
    } while (0)

__global__ __launch_bounds__(NTHREADS, 5)   // cap ~102 regs, 20 warps/SM
void speccnn1d_kernel(const float* __restrict__ x,
                      const float* __restrict__ kern,
                      float* __restrict__ out) {
    __shared__ u64 xs2[TILE_O + KW];                     // 48 * 8B, {v,v} dup

    const int tid = threadIdx.x;
    const int b   = blockIdx.y;
    const int o0  = blockIdx.x * TILE_O;

    // ---- stage x window duplicated ----
    {
        const float* xb = x + (size_t)b * LSEQ;
        if (tid < TILE_O + KW - 1) {                     // 47 elements
            int xi = o0 + tid;
            float v = (xi < LSEQ) ? __ldg(&xb[xi]) : 0.0f;
            xs2[tid] = pack2(v, v);
        }
    }

    // thread -> (channel pair, o-subgroup); og warp-uniform => broadcast LDS
    const int f0 = ((tid & 31) << 1) + (((tid >> 5) & 1) << 6);  // even, 0..126
    const int og = tid >> 6;                                     // 0..1

    // ---- 2 weight rows -> 16 packed pairs (32 regs) ----
    u64 w[KW];
    {
        const float4* r0 = reinterpret_cast<const float4*>(kern + (size_t)f0 * KW);
        const float4* r1 = reinterpret_cast<const float4*>(kern + (size_t)(f0 + 1) * KW);
        #pragma unroll
        for (int q = 0; q < 4; q++) {
            float4 a = __ldg(&r0[q]);
            float4 c = __ldg(&r1[q]);
            w[q * 4 + 0] = pack2(a.x, c.x);
            w[q * 4 + 1] = pack2(a.y, c.y);
            w[q * 4 + 2] = pack2(a.z, c.z);
            w[q * 4 + 3] = pack2(a.w, c.w);
        }
    }
    __syncthreads();

    const int lo = og * BO;                              // local o: 0 or 16
    const int o  = o0 + lo;
    const u64* xp = &xs2[lo];

    // ---- diagonal over 16 outputs, named scalar accumulators ----
    u64 A0, A1, A2, A3, A4, A5, A6, A7;
    u64 A8, A9, A10, A11, A12, A13, A14, A15;

    #pragma unroll
    for (int i = 0; i < XWIN; i++) {                     // 31 broadcast LDS.64
        u64 xv = xp[i];
        DIAG1(A0,  0)  DIAG1(A1,  1)  DIAG1(A2,  2)  DIAG1(A3,  3)
        DIAG1(A4,  4)  DIAG1(A5,  5)  DIAG1(A6,  6)  DIAG1(A7,  7)
        DIAG1(A8,  8)  DIAG1(A9,  9)  DIAG1(A10, 10) DIAG1(A11, 11)
        DIAG1(A12, 12) DIAG1(A13, 13) DIAG1(A14, 14) DIAG1(A15, 15)
    }

    float2* po = reinterpret_cast<float2*>(
        out + (size_t)b * OUT_LEN * FCH + (size_t)o * FCH + f0);

    if (o + BO <= OUT_LEN) {                             // fast path
        STORE1(A0,  0);  STORE1(A1,  1);  STORE1(A2,  2);  STORE1(A3,  3);
        STORE1(A4,  4);  STORE1(A5,  5);  STORE1(A6,  6);  STORE1(A7,  7);
        STORE1(A8,  8);  STORE1(A9,  9);  STORE1(A10, 10); STORE1(A11, 11);
        STORE1(A12, 12); STORE1(A13, 13); STORE1(A14, 14); STORE1(A15, 15);
    } else {
        const int rem = OUT_LEN - o;                     // valid outputs
        if (0  < rem) STORE1(A0,  0);
        if (1  < rem) STORE1(A1,  1);
        if (2  < rem) STORE1(A2,  2);
        if (3  < rem) STORE1(A3,  3);
        if (4  < rem) STORE1(A4,  4);
        if (5  < rem) STORE1(A5,  5);
        if (6  < rem) STORE1(A6,  6);
        if (7  < rem) STORE1(A7,  7);
        if (8  < rem) STORE1(A8,  8);
        if (9  < rem) STORE1(A9,  9);
        if (10 < rem) STORE1(A10, 10);
        if (11 < rem) STORE1(A11, 11);
        if (12 < rem) STORE1(A12, 12);
        if (13 < rem) STORE1(A13, 13);
        if (14 < rem) STORE1(A14, 14);
        if (15 < rem) STORE1(A15, 15);
    }
}

extern "C" void kernel_launch(void* const* d_in, const int* in_sizes, int n_in,
                              void* d_out, int out_size) {
    const float* x    = (const float*)d_in[0];   // (64, 16384) fp32
    const float* kern = (const float*)d_in[1];   // (128, 16)  fp32
    float* out        = (float*)d_out;           // (64, 16369, 128) fp32

    dim3 grid((OUT_LEN + TILE_O - 1) / TILE_O, BATCH);   // (512, 64)
    speccnn1d_kernel<<<grid, NTHREADS>>>(x, kern, out);
}

// round 10
// speedup vs baseline: 1.0900x; 1.0112x over previous
#include <cuda_runtime.h>
#include <cstdint>

#define BATCH    64
#define LSEQ     16384
#define FCH      128
#define KW       16
#define OUT_LEN  16369           // (16384 - 16) + 1
#define TILE_O   32              // o per block
#define NTHREADS 128             // 4 warps
#define BO       8               // o per chunk (8 live acc pairs max)
#define XWIN     (BO + KW - 1)   // 23

typedef unsigned long long u64;

__device__ __forceinline__ u64 pack2(float lo, float hi) {
    u64 r;
    asm("mov.b64 %0, {%1, %2};" : "=l"(r) : "f"(lo), "f"(hi));
    return r;
}
__device__ __forceinline__ void ffma2(u64& d, u64 a, u64 b) {
    asm("fma.rn.f32x2 %0, %1, %2, %0;" : "+l"(d) : "l"(a), "l"(b));
}
__device__ __forceinline__ void fmul2(u64& d, u64 a, u64 b) {
    asm("mul.rn.f32x2 %0, %1, %2;" : "=l"(d) : "l"(a), "l"(b));
}
__device__ __forceinline__ void unpack2(u64 v, float& lo, float& hi) {
    asm("mov.b64 {%0, %1}, %2;" : "=f"(lo), "=f"(hi) : "l"(v));
}

// one diagonal update for output J at window step i (both compile-time)
#define DIAG1(ACC, J)                                            \
    if (i == (J)) fmul2(ACC, xv, w[0]);                          \
    else if (i > (J) && i < (J) + KW) ffma2(ACC, xv, w[i - (J)]);

// relu + STG.64 for output J
#define STORE1(ACC, J)                                           \
    do {                                                         \
        float l_, h_;                                            \
        unpack2(ACC, l_, h_);                                    \
        float2 r_;                                               \
        r_.x = fmaxf(l_, 0.f);                                   \
        r_.y = fmaxf(h_, 0.f);                                   \
        po[(J) * (FCH / 2)] = r_;                                \
    } while (0)

__global__ __launch_bounds__(NTHREADS, 5)   // reg cap ~102, 20 warps/SM
void speccnn1d_kernel(const float* __restrict__ x,
                      const float* __restrict__ kern,
                      float* __restrict__ out) {
    __shared__ u64 xs2[TILE_O + KW];                     // 48 * 8B, {v,v} dup

    const int tid = threadIdx.x;
    const int b   = blockIdx.y;
    const int o0  = blockIdx.x * TILE_O;

    // ---- stage x window duplicated ----
    {
        const float* xb = x + (size_t)b * LSEQ;
        if (tid < TILE_O + KW - 1) {                     // 47 elements
            int xi = o0 + tid;
            float v = (xi < LSEQ) ? __ldg(&xb[xi]) : 0.0f;
            xs2[tid] = pack2(v, v);
        }
    }

    // thread -> (channel pair, o-subgroup); og warp-uniform => broadcast LDS
    const int f0 = ((tid & 31) << 1) + (((tid >> 5) & 1) << 6);  // even, 0..126
    const int og = tid >> 6;                                     // 0..1

    // ---- 2 weight rows -> 16 packed pairs (32 regs) ----
    u64 w[KW];
    {
        const float4* r0 = reinterpret_cast<const float4*>(kern + (size_t)f0 * KW);
        const float4* r1 = reinterpret_cast<const float4*>(kern + (size_t)(f0 + 1) * KW);
        #pragma unroll
        for (int q = 0; q < 4; q++) {
            float4 a = __ldg(&r0[q]);
            float4 c = __ldg(&r1[q]);
            w[q * 4 + 0] = pack2(a.x, c.x);
            w[q * 4 + 1] = pack2(a.y, c.y);
            w[q * 4 + 2] = pack2(a.z, c.z);
            w[q * 4 + 3] = pack2(a.w, c.w);
        }
    }
    __syncthreads();

    float* outb = out + (size_t)b * OUT_LEN * FCH + f0;

    // ---- two 8-o chunks per thread; 8 live acc pairs per chunk ----
    #pragma unroll
    for (int c = 0; c < 2; c++) {
        const int lo = og * 16 + c * BO;                 // local o
        const int o  = o0 + lo;
        const u64* xp = &xs2[lo];

        u64 A0, A1, A2, A3, A4, A5, A6, A7;

        #pragma unroll
        for (int i = 0; i < XWIN; i++) {                 // 23 broadcast LDS.64
            u64 xv = xp[i];
            DIAG1(A0, 0)  DIAG1(A1, 1)  DIAG1(A2, 2)  DIAG1(A3, 3)
            DIAG1(A4, 4)  DIAG1(A5, 5)  DIAG1(A6, 6)  DIAG1(A7, 7)
        }

        float2* po = reinterpret_cast<float2*>(outb + (size_t)o * FCH);

        if (o + BO <= OUT_LEN) {                         // fast path
            STORE1(A0, 0); STORE1(A1, 1); STORE1(A2, 2); STORE1(A3, 3);
            STORE1(A4, 4); STORE1(A5, 5); STORE1(A6, 6); STORE1(A7, 7);
        } else {
            const int rem = OUT_LEN - o;
            if (0 < rem) STORE1(A0, 0);
            if (1 < rem) STORE1(A1, 1);
            if (2 < rem) STORE1(A2, 2);
            if (3 < rem) STORE1(A3, 3);
            if (4 < rem) STORE1(A4, 4);
            if (5 < rem) STORE1(A5, 5);
            if (6 < rem) STORE1(A6, 6);
            if (7 < rem) STORE1(A7, 7);
        }
    }
}

extern "C" void kernel_launch(void* const* d_in, const int* in_sizes, int n_in,
                              void* d_out, int out_size) {
    const float* x    = (const float*)d_in[0];   // (64, 16384) fp32
    const float* kern = (const float*)d_in[1];   // (128, 16)  fp32
    float* out        = (float*)d_out;           // (64, 16369, 128) fp32

    dim3 grid((OUT_LEN + TILE_O - 1) / TILE_O, BATCH);   // (512, 64)
    speccnn1d_kernel<<<grid, NTHREADS>>>(x, kern, out);
}

// round 12
// speedup vs baseline: 1.2375x; 1.1353x over previous
#include <cuda_runtime.h>
#include <cstdint>

#define BATCH    64
#define LSEQ     16384
#define FCH      128
#define KW       16
#define OUT_LEN  16369            // (16384 - 16) + 1
#define TILE_O   32               // o per block (2 warp-rows of 16)
#define NTHREADS 256              // 8 warps: og = wid>>2 (0..1), fg = wid&3 (0..3)
#define XWIN     (TILE_O + KW - 1)  // 47

// split v into tf32 hi + tf32 lo (3xTF32 emulation parts)
__device__ __forceinline__ void split_tf32(float v, uint32_t& hi, uint32_t& lo) {
    uint32_t h;
    asm("cvt.rna.tf32.f32 %0, %1;" : "=r"(h) : "f"(v));
    float rem = v - __uint_as_float(h);      // tf32 bits are valid fp32
    uint32_t l;
    asm("cvt.rna.tf32.f32 %0, %1;" : "=r"(l) : "f"(rem));
    hi = h; lo = l;
}

// D(16x8) += A(16x8) * B(8x8)^T  -- tf32 inputs, fp32 accumulate
__device__ __forceinline__ void mma_16n8k8(float c[4], const uint32_t a[4],
                                           const uint32_t b[2]) {
    asm volatile(
        "mma.sync.aligned.m16n8k8.row.col.f32.tf32.tf32.f32 "
        "{%0,%1,%2,%3}, {%4,%5,%6,%7}, {%8,%9}, {%0,%1,%2,%3};"
        : "+f"(c[0]), "+f"(c[1]), "+f"(c[2]), "+f"(c[3])
        : "r"(a[0]), "r"(a[1]), "r"(a[2]), "r"(a[3]), "r"(b[0]), "r"(b[1]));
}

__global__ __launch_bounds__(NTHREADS, 2)   // cap 128 regs: clean-codegen regime
void speccnn1d_mma_kernel(const float* __restrict__ x,
                          const float* __restrict__ kern,
                          float* __restrict__ out) {
    __shared__ float xs[XWIN];

    const int tid  = threadIdx.x;
    const int lane = tid & 31;
    const int wid  = tid >> 5;
    const int b    = blockIdx.y;
    const int o0   = blockIdx.x * TILE_O;

    // ---- stage x window ----
    if (tid < XWIN) {
        int xi = o0 + tid;
        xs[tid] = (xi < LSEQ) ? __ldg(&x[(size_t)b * LSEQ + xi]) : 0.0f;
    }
    __syncthreads();

    const int fg = wid & 3;                  // f-group: 32 channels
    const int og = wid >> 2;                 // o-group: 16 rows
    const int t  = lane & 3;                 // threadID in group (k / col-pair)
    const int g  = lane >> 2;                // groupID (row / n)

    // ---- B fragments (weights), 3xTF32 split, resident in regs ----
    // B(k,n) = W[fg*32 + nb*8 + n][k];  b0: k = t, b1: k = t+4 (per 8-k step)
    uint32_t Bb[4][2][2], Bs[4][2][2];
    #pragma unroll
    for (int nb = 0; nb < 4; nb++) {
        const float* wr = kern + (size_t)(fg * 32 + nb * 8 + g) * KW;
        #pragma unroll
        for (int k = 0; k < 2; k++) {
            split_tf32(__ldg(&wr[k * 8 + t]),     Bb[nb][k][0], Bs[nb][k][0]);
            split_tf32(__ldg(&wr[k * 8 + t + 4]), Bb[nb][k][1], Bs[nb][k][1]);
        }
    }

    // ---- accumulators: 4 n-blocks x 4 regs ----
    float C[4][4];
    #pragma unroll
    for (int nb = 0; nb < 4; nb++)
        #pragma unroll
        for (int j = 0; j < 4; j++) C[nb][j] = 0.0f;

    // ---- mainloop: 2 k-steps of 8 ----
    #pragma unroll
    for (int k = 0; k < 2; k++) {
        // A fragment: A(row, kk) = xs[og*16 + row + kk]  (im2col, free)
        const int base = og * 16 + g;
        const int kc   = k * 8 + t;
        uint32_t Ab[4], Al[4];
        split_tf32(xs[base + kc],         Ab[0], Al[0]);   // (row,   k)
        split_tf32(xs[base + 8 + kc],     Ab[1], Al[1]);   // (row+8, k)
        split_tf32(xs[base + kc + 4],     Ab[2], Al[2]);   // (row,   k+4)
        split_tf32(xs[base + 8 + kc + 4], Ab[3], Al[3]);   // (row+8, k+4)

        #pragma unroll
        for (int nb = 0; nb < 4; nb++) {
            mma_16n8k8(C[nb], Ab, Bb[nb][k]);              // big * big
            mma_16n8k8(C[nb], Ab, Bs[nb][k]);              // big * small
            mma_16n8k8(C[nb], Al, Bb[nb][k]);              // small * big
        }
    }

    // ---- epilogue: relu + stores ----
    // C layout: c0,c1 = (row=g, f=2t, 2t+1); c2,c3 = (row=g+8, same f)
    const int r0 = o0 + og * 16 + g;
    float* orow = out + ((size_t)b * OUT_LEN + r0) * FCH + fg * 32 + 2 * t;

    if (r0 < OUT_LEN) {
        #pragma unroll
        for (int nb = 0; nb < 4; nb++) {
            float2 v;
            v.x = fmaxf(C[nb][0], 0.0f);
            v.y = fmaxf(C[nb][1], 0.0f);
            *reinterpret_cast<float2*>(orow + nb * 8) = v;
        }
    }
    if (r0 + 8 < OUT_LEN) {
        float* orow2 = orow + (size_t)8 * FCH;
        #pragma unroll
        for (int nb = 0; nb < 4; nb++) {
            float2 v;
            v.x = fmaxf(C[nb][2], 0.0f);
            v.y = fmaxf(C[nb][3], 0.0f);
            *reinterpret_cast<float2*>(orow2 + nb * 8) = v;
        }
    }
}

extern "C" void kernel_launch(void* const* d_in, const int* in_sizes, int n_in,
                              void* d_out, int out_size) {
    const float* x    = (const float*)d_in[0];   // (64, 16384) fp32
    const float* kern = (const float*)d_in[1];   // (128, 16)  fp32
    float* out        = (float*)d_out;           // (64, 16369, 128) fp32

    dim3 grid((OUT_LEN + TILE_O - 1) / TILE_O, BATCH);   // (512, 64)
    speccnn1d_mma_kernel<<<grid, NTHREADS>>>(x, kern, out);
}

// round 13
// speedup vs baseline: 1.9064x; 1.5405x over previous
#include <cuda_runtime.h>
#include <cstdint>

#define BATCH    64
#define LSEQ     16384
#define FCH      128
#define KW       16
#define OUT_LEN  16369            // (16384 - 16) + 1
#define TILE_O   128              // o per block (8 warps x 4 subtiles of 16)
#define NTHREADS 256              // 8 warps: og = wid>>2 (0..1), fg = wid&3
#define XWIN     (TILE_O + KW - 1)  // 143

// split v into tf32 hi + tf32 lo (3xTF32 emulation parts)
__device__ __forceinline__ void split_tf32(float v, uint32_t& hi, uint32_t& lo) {
    uint32_t h;
    asm("cvt.rna.tf32.f32 %0, %1;" : "=r"(h) : "f"(v));
    float rem = v - __uint_as_float(h);      // tf32 bits are valid fp32
    uint32_t l;
    asm("cvt.rna.tf32.f32 %0, %1;" : "=r"(l) : "f"(rem));
    hi = h; lo = l;
}

// D(16x8) += A(16x8) * B(8x8)^T  -- tf32 inputs, fp32 accumulate
__device__ __forceinline__ void mma_16n8k8(float c[4], const uint32_t a[4],
                                           const uint32_t b[2]) {
    asm volatile(
        "mma.sync.aligned.m16n8k8.row.col.f32.tf32.tf32.f32 "
        "{%0,%1,%2,%3}, {%4,%5,%6,%7}, {%8,%9}, {%0,%1,%2,%3};"
        : "+f"(c[0]), "+f"(c[1]), "+f"(c[2]), "+f"(c[3])
        : "r"(a[0]), "r"(a[1]), "r"(a[2]), "r"(a[3]), "r"(b[0]), "r"(b[1]));
}

__global__ __launch_bounds__(NTHREADS, 2)   // cap 128 regs: clean-codegen regime
void speccnn1d_mma_kernel(const float* __restrict__ x,
                          const float* __restrict__ kern,
                          float* __restrict__ out) {
    __shared__ uint32_t xs_hi[XWIN];
    __shared__ uint32_t xs_lo[XWIN];

    const int tid  = threadIdx.x;
    const int lane = tid & 31;
    const int wid  = tid >> 5;
    const int b    = blockIdx.y;
    const int o0   = blockIdx.x * TILE_O;

    // ---- stage x window, pre-split into tf32 hi/lo (once per CTA) ----
    if (tid < XWIN) {
        int xi = o0 + tid;
        float v = (xi < LSEQ) ? __ldg(&x[(size_t)b * LSEQ + xi]) : 0.0f;
        uint32_t h, l;
        split_tf32(v, h, l);
        xs_hi[tid] = h;
        xs_lo[tid] = l;
    }
    __syncthreads();

    const int fg = wid & 3;                  // f-group: 32 channels
    const int og = wid >> 2;                 // o-group: 64 rows (4 subtiles)
    const int t  = lane & 3;                 // threadID in group
    const int g  = lane >> 2;                // groupID

    // ---- B fragments (weights), 3xTF32 split, resident in regs ----
    uint32_t Bb[4][2][2], Bs[4][2][2];
    #pragma unroll
    for (int nb = 0; nb < 4; nb++) {
        const float* wr = kern + (size_t)(fg * 32 + nb * 8 + g) * KW;
        #pragma unroll
        for (int k = 0; k < 2; k++) {
            split_tf32(__ldg(&wr[k * 8 + t]),     Bb[nb][k][0], Bs[nb][k][0]);
            split_tf32(__ldg(&wr[k * 8 + t + 4]), Bb[nb][k][1], Bs[nb][k][1]);
        }
    }

    // ---- 4 o-subtiles of 16 per warp ----
    #pragma unroll
    for (int sub = 0; sub < 4; sub++) {
        const int obase = og * 64 + sub * 16;      // local o of this subtile

        float C[4][4];
        #pragma unroll
        for (int nb = 0; nb < 4; nb++)
            #pragma unroll
            for (int j = 0; j < 4; j++) C[nb][j] = 0.0f;

        #pragma unroll
        for (int k = 0; k < 2; k++) {
            const int base = obase + g;
            const int kc   = k * 8 + t;
            uint32_t Ab[4], Al[4];
            Ab[0] = xs_hi[base + kc];          Al[0] = xs_lo[base + kc];
            Ab[1] = xs_hi[base + 8 + kc];      Al[1] = xs_lo[base + 8 + kc];
            Ab[2] = xs_hi[base + kc + 4];      Al[2] = xs_lo[base + kc + 4];
            Ab[3] = xs_hi[base + 8 + kc + 4];  Al[3] = xs_lo[base + 8 + kc + 4];

            #pragma unroll
            for (int nb = 0; nb < 4; nb++) {
                mma_16n8k8(C[nb], Ab, Bb[nb][k]);   // big * big
                mma_16n8k8(C[nb], Ab, Bs[nb][k]);   // big * small
                mma_16n8k8(C[nb], Al, Bb[nb][k]);   // small * big
            }
        }

        // ---- epilogue: relu + stores ----
        // C layout: c0,c1 = (row=g, f=2t,2t+1); c2,c3 = (row=g+8)
        const int r0 = o0 + obase + g;
        float* orow = out + ((size_t)b * OUT_LEN + r0) * FCH + fg * 32 + 2 * t;

        if (r0 < OUT_LEN) {
            #pragma unroll
            for (int nb = 0; nb < 4; nb++) {
                float2 v;
                v.x = fmaxf(C[nb][0], 0.0f);
                v.y = fmaxf(C[nb][1], 0.0f);
                *reinterpret_cast<float2*>(orow + nb * 8) = v;
            }
        }
        if (r0 + 8 < OUT_LEN) {
            float* orow2 = orow + (size_t)8 * FCH;
            #pragma unroll
            for (int nb = 0; nb < 4; nb++) {
                float2 v;
                v.x = fmaxf(C[nb][2], 0.0f);
                v.y = fmaxf(C[nb][3], 0.0f);
                *reinterpret_cast<float2*>(orow2 + nb * 8) = v;
            }
        }
    }
}

extern "C" void kernel_launch(void* const* d_in, const int* in_sizes, int n_in,
                              void* d_out, int out_size) {
    const float* x    = (const float*)d_in[0];   // (64, 16384) fp32
    const float* kern = (const float*)d_in[1];   // (128, 16)  fp32
    float* out        = (float*)d_out;           // (64, 16369, 128) fp32

    dim3 grid((OUT_LEN + TILE_O - 1) / TILE_O, BATCH);   // (128, 64)
    speccnn1d_mma_kernel<<<grid, NTHREADS>>>(x, kern, out);
}